// round 16
// baseline (speedup 1.0000x reference)
#include <cuda_runtime.h>
#include <cuda_bf16.h>
#include <math.h>
#include <stdint.h>

// ---------------- problem constants ----------------
#define NLAYER 18
#define WIDTH  1024
#define NHEAD  8
#define HD     256
#define MLPD   4096
#define AHORIZ 50
#define ADIM   32
#define NB     4
#define PREF   968
#define TOT    (PREF + AHORIZ)   // 1018
#define NROWS  (NB * AHORIZ)     // 200

enum { EP_NONE = 0, EP_BIAS, EP_BIAS_SILU, EP_BIAS_SCALE, EP_ACC, EP_SCALE, EP_SPLIT,
       EP_EXPSPLITSUM, EP_DIVSPLIT };
enum { BMODE_NORMAL = 0, BMODE_TRANS_SEG = 1, BMODE_SEG = 2 };

// ---------------- device scratch ----------------
__device__ float g_time_emb[NB * WIDTH];
__device__ float g_t1[NB * WIDTH];
__device__ float g_cond[NB * WIDTH];
__device__ float g_scale1[NLAYER * NB * WIDTH];
__device__ float g_scale2[NLAYER * NB * WIDTH];
__device__ float g_fscale[NB * WIDTH];
__device__ float g_h[NROWS * WIDTH];
__device__ float g_q[NB * NHEAD * AHORIZ * HD];   // [b][h][s][d] fp32 (pre-rope)
__device__ float g_k[NROWS * HD];
__device__ float g_v[NROWS * HD];
__device__ float g_rsum[NB * NHEAD * AHORIZ];     // per-row exp sums

// pre-split bf16 operand planes [2][...]
__device__ __nv_bfloat16 g_nsp[2 * NROWS * WIDTH];
__device__ __nv_bfloat16 g_qsp[2 * NB * NHEAD * AHORIZ * HD];
__device__ __nv_bfloat16 g_psp[2 * NB * NHEAD * AHORIZ * 1024];  // exp vals; pads stay 0
__device__ __nv_bfloat16 g_attsp[2 * NROWS * NHEAD * HD];
__device__ __nv_bfloat16 g_actsp[2 * NROWS * MLPD];

#define SP_N   (NROWS * WIDTH)
#define SP_Q   (NB * NHEAD * AHORIZ * HD)
#define SP_P   (NB * NHEAD * AHORIZ * 1024)
#define SP_ATT (NROWS * NHEAD * HD)
#define SP_ACT (NROWS * MLPD)

__device__ __forceinline__ float fast_gelu(float x) {
    float u = 0.7978845608028654f * (x + 0.044715f * x * x * x);
    float e = __expf(2.f * u);
    float t = 1.f - __fdividef(2.f, e + 1.f);
    return 0.5f * x * (1.f + t);
}

__device__ __forceinline__ uint32_t s2u(const void* p) {
    return (uint32_t)__cvta_generic_to_shared(p);
}
__device__ __forceinline__ void ldsm4(uint32_t* r, uint32_t addr) {
    asm volatile("ldmatrix.sync.aligned.m8n8.x4.shared.b16 {%0,%1,%2,%3}, [%4];"
                 : "=r"(r[0]), "=r"(r[1]), "=r"(r[2]), "=r"(r[3]) : "r"(addr));
}
__device__ __forceinline__ void ldsm4t(uint32_t* r, uint32_t addr) {
    asm volatile("ldmatrix.sync.aligned.m8n8.x4.trans.shared.b16 {%0,%1,%2,%3}, [%4];"
                 : "=r"(r[0]), "=r"(r[1]), "=r"(r[2]), "=r"(r[3]) : "r"(addr));
}
__device__ __forceinline__ void mma16816(float* c, const uint32_t* a, const uint32_t* b) {
    asm volatile(
        "mma.sync.aligned.m16n8k16.row.col.f32.bf16.bf16.f32 "
        "{%0,%1,%2,%3}, {%4,%5,%6,%7}, {%8,%9}, {%0,%1,%2,%3};"
        : "+f"(c[0]), "+f"(c[1]), "+f"(c[2]), "+f"(c[3])
        : "r"(a[0]), "r"(a[1]), "r"(a[2]), "r"(a[3]), "r"(b[0]), "r"(b[1]));
}
__device__ __forceinline__ void bsplit(float x, __nv_bfloat16& hi, __nv_bfloat16& lo) {
    hi = __float2bfloat16(x);
    lo = __float2bfloat16(x - __bfloat162float(hi));
}
__device__ __forceinline__ void bsplit2(float x0, float x1, uint32_t& hi2, uint32_t& lo2) {
    __nv_bfloat16 h0, l0, h1, l1;
    bsplit(x0, h0, l0); bsplit(x1, h1, l1);
    __nv_bfloat162 hp = __nv_bfloat162(h0, h1), lp = __nv_bfloat162(l0, l1);
    hi2 = *(uint32_t*)&hp; lo2 = *(uint32_t*)&lp;
}

#define ASTR 40
#define BSTR 72

// ================= split-bf16 tensor-core GEMM, BMx64x32 tile, 2-deep prefetch ==========
template <int BM, bool APRE>
__global__ void __launch_bounds__(256, 2) mma_gemm(
    const void* __restrict__ Aptr, long lda, long sAb, long spA,
    const float* __restrict__ B1, long ldb1, long sB1b,
    const float* __restrict__ B2, long ldb2, long sB2b,
    const float* __restrict__ B3, long ldb3,
    float* __restrict__ C1, long ldc1,
    float* __restrict__ C2, long ldc2,
    float* __restrict__ C3, long ldc3,
    long sCb,
    __nv_bfloat16* __restrict__ Csp, long spC,
    float* __restrict__ rsum,
    int M, int K, int nk, int tmax, int bmode,
    int xs1, int xs2, int N1, int N2, int N3,
    const float* __restrict__ aux, int ep, float alpha, int remap)
{
    constexpr int TPR = 256 / BM;
    constexpr int FPT = 32 / TPR;
    constexpr int NV4 = FPT / 8;
    constexpr int MFRAG = BM / 64;

    int z = blockIdx.z;
    int ks = z % nk, b = z / nk;

    const float* Af = (const float*)Aptr + (long)b * sAb;
    const __nv_bfloat16* Abf = (const __nv_bfloat16*)Aptr + (long)b * sAb;
    const float* Bp1 = B1 + (long)b * sB1b;
    const float* Bp2 = B2 ? B2 + (long)b * sB2b : (const float*)0;

    const float* B = Bp1;
    float* C = C1;
    long ldb = ldb1, ldc = ldc1;
    int n0, Nseg = N1;
    int xb = blockIdx.x;
    int rm = remap;
    if (bmode == BMODE_NORMAL) {
        if (xb < xs1) { n0 = xb * 64; }
        else if (xb < xs2) { B = B2; C = C2; ldb = ldb2; ldc = ldc2; Nseg = N2; n0 = (xb - xs1) * 64; rm = 0; }
        else { B = B3; C = C3; ldb = ldb3; ldc = ldc3; Nseg = N3; n0 = (xb - xs2) * 64; rm = 0; }
    } else {
        n0 = xb * 64;
    }
    C += (long)b * sCb;
    __nv_bfloat16* Cs = Csp ? Csp + (long)b * sCb : (__nv_bfloat16*)0;

    extern __shared__ __nv_bfloat16 sm[];
    __nv_bfloat16* sAb_ = sm;
    __nv_bfloat16* sBb_ = sm + 4 * BM * ASTR;
#define SA(st, pl, m) (sAb_ + (((st) * 2 + (pl)) * BM + (m)) * ASTR)
#define SB(st, pl, k) (sBb_ + (((st) * 2 + (pl)) * 32 + (k)) * BSTR)

    int tid = threadIdx.x;
    int m0 = blockIdx.y * BM;
    int warp = tid >> 5, lane = tid & 31;
    int wm = (warp >> 1) * (BM / 4), wn = (warp & 1) * 32;

    float acc[MFRAG][4][4];
#pragma unroll
    for (int mi = 0; mi < MFRAG; mi++)
#pragma unroll
        for (int ni = 0; ni < 4; ni++)
#pragma unroll
            for (int e = 0; e < 4; e++) acc[mi][ni][e] = 0.f;

    const float4 fz = make_float4(0.f, 0.f, 0.f, 0.f);

    int kbeg = ks * (K / nk);
    int kend = kbeg + (K / nk);

    int arow = tid / TPR, ak = (tid % TPR) * FPT;
    int bkr = tid >> 3, bn8 = (tid & 7) * 8;
    int ttl = tid >> 2, tk = (tid & 3) * 8;

    float ra0[APRE ? 1 : FPT], ra1[APRE ? 1 : FPT];
    uint4 rahi0[APRE ? NV4 : 1], ralo0[APRE ? NV4 : 1];
    uint4 rahi1[APRE ? NV4 : 1], ralo1[APRE ? NV4 : 1];
    float4 rb00, rb01, rb10, rb11;

    auto loadA = [&](int k0, uint4* rahi, uint4* ralo, float* ra) {
        int m = m0 + arow;
        if constexpr (APRE) {
            if (m < M) {
                const __nv_bfloat16* src = Abf + (long)m * lda + k0 + ak;
#pragma unroll
                for (int v = 0; v < NV4; v++) {
                    rahi[v] = ((const uint4*)src)[v];
                    ralo[v] = ((const uint4*)(src + spA))[v];
                }
            } else {
                uint4 z4 = make_uint4(0, 0, 0, 0);
#pragma unroll
                for (int v = 0; v < NV4; v++) { rahi[v] = z4; ralo[v] = z4; }
            }
        } else {
            if (m < M) {
                const float* src = Af + (long)m * lda + k0 + ak;
#pragma unroll
                for (int f = 0; f < FPT / 4; f++)
                    *(float4*)(ra + 4 * f) = *(const float4*)(src + 4 * f);
            } else {
#pragma unroll
                for (int f = 0; f < FPT; f++) ra[f] = 0.f;
            }
        }
    };
    auto loadB = [&](int k0, float4& rb0, float4& rb1) {
        if (bmode == BMODE_NORMAL) {
            int n = n0 + bn8;
            if (n < Nseg) {
                const float* src = B + (long)(k0 + bkr) * ldb + n;
                rb0 = *(const float4*)src;
                rb1 = *(const float4*)(src + 4);
            } else { rb0 = fz; rb1 = fz; }
        } else if (bmode == BMODE_TRANS_SEG) {
            int t = n0 + ttl;
            if (t < tmax) {
                const float* src = (t < PREF) ? Bp1 + (long)t * ldb1
                                              : Bp2 + (long)(t - PREF) * ldb1;
                rb0 = *(const float4*)(src + k0 + tk);
                rb1 = *(const float4*)(src + k0 + tk + 4);
            } else { rb0 = fz; rb1 = fz; }
        } else {
            int t = k0 + bkr;
            if (t < tmax) {
                const float* src = (t < PREF) ? Bp1 + (long)t * ldb1
                                              : Bp2 + (long)(t - PREF) * ldb1;
                rb0 = *(const float4*)(src + n0 + bn8);
                rb1 = *(const float4*)(src + n0 + bn8 + 4);
            } else { rb0 = fz; rb1 = fz; }
        }
    };
    auto storeTiles = [&](int st, uint4* rahi, uint4* ralo, float* ra,
                          float4& rb0, float4& rb1) {
        if constexpr (APRE) {
            uint4* dh = (uint4*)(SA(st, 0, arow) + ak);
            uint4* dl = (uint4*)(SA(st, 1, arow) + ak);
#pragma unroll
            for (int v = 0; v < NV4; v++) { dh[v] = rahi[v]; dl[v] = ralo[v]; }
        } else {
            uint32_t* pAh = (uint32_t*)(SA(st, 0, arow) + ak);
            uint32_t* pAl = (uint32_t*)(SA(st, 1, arow) + ak);
#pragma unroll
            for (int j = 0; j < FPT / 2; j++) {
                uint32_t hi2, lo2;
                bsplit2(ra[2 * j], ra[2 * j + 1], hi2, lo2);
                pAh[j] = hi2; pAl[j] = lo2;
            }
        }
        float bv[8] = {rb0.x, rb0.y, rb0.z, rb0.w, rb1.x, rb1.y, rb1.z, rb1.w};
        if (bmode == BMODE_TRANS_SEG) {
#pragma unroll
            for (int j = 0; j < 8; j++) {
                __nv_bfloat16 hi, lo; bsplit(bv[j], hi, lo);
                SB(st, 0, tk + j)[ttl] = hi; SB(st, 1, tk + j)[ttl] = lo;
            }
        } else {
            uint32_t h4[4], l4[4];
#pragma unroll
            for (int j = 0; j < 4; j++) bsplit2(bv[2 * j], bv[2 * j + 1], h4[j], l4[j]);
            *(uint4*)(SB(st, 0, bkr) + bn8) = make_uint4(h4[0], h4[1], h4[2], h4[3]);
            *(uint4*)(SB(st, 1, bkr) + bn8) = make_uint4(l4[0], l4[1], l4[2], l4[3]);
        }
    };

    int r = lane & 15, cg = lane >> 4;

    auto compute = [&](int st) {
#pragma unroll
        for (int kh = 0; kh < 2; kh++) {
            uint32_t bhf[8], blf[8];
#pragma unroll
            for (int g = 0; g < 2; g++) {
                ldsm4t(&bhf[g * 4], s2u(SB(st, 0, kh * 16 + r) + wn + g * 16 + cg * 8));
                ldsm4t(&blf[g * 4], s2u(SB(st, 1, kh * 16 + r) + wn + g * 16 + cg * 8));
            }
#pragma unroll
            for (int mi = 0; mi < MFRAG; mi++) {
                uint32_t ah[4], al[4];
                ldsm4(ah, s2u(SA(st, 0, wm + mi * 16 + r) + kh * 16 + cg * 8));
                ldsm4(al, s2u(SA(st, 1, wm + mi * 16 + r) + kh * 16 + cg * 8));
#pragma unroll
                for (int ni = 0; ni < 4; ni++) {
                    mma16816(acc[mi][ni], ah, &bhf[ni * 2]);
                    mma16816(acc[mi][ni], ah, &blf[ni * 2]);
                    mma16816(acc[mi][ni], al, &bhf[ni * 2]);
                }
            }
        }
    };

    loadA(kbeg, rahi0, ralo0, ra0); loadB(kbeg, rb00, rb01);
    if (kbeg + 32 < kend) { loadA(kbeg + 32, rahi1, ralo1, ra1); loadB(kbeg + 32, rb10, rb11); }

    for (int k0 = kbeg; k0 < kend; k0 += 64) {
        storeTiles(0, rahi0, ralo0, ra0, rb00, rb01);
        __syncthreads();
        if (k0 + 64 < kend) { loadA(k0 + 64, rahi0, ralo0, ra0); loadB(k0 + 64, rb00, rb01); }
        compute(0);
        if (k0 + 32 >= kend) break;
        storeTiles(1, rahi1, ralo1, ra1, rb10, rb11);
        __syncthreads();
        if (k0 + 96 < kend) { loadA(k0 + 96, rahi1, ralo1, ra1); loadB(k0 + 96, rb10, rb11); }
        compute(1);
    }

    if (ep == EP_EXPSPLITSUM) {
        // exp epilogue: e = exp(v*alpha); split-write e into Cs planes; accumulate row sums
        float rp[MFRAG][2];
#pragma unroll
        for (int mi = 0; mi < MFRAG; mi++) { rp[mi][0] = 0.f; rp[mi][1] = 0.f; }
#pragma unroll
        for (int mi = 0; mi < MFRAG; mi++)
#pragma unroll
            for (int ni = 0; ni < 4; ni++)
#pragma unroll
                for (int e = 0; e < 4; e++) {
                    int m = m0 + wm + mi * 16 + (lane >> 2) + ((e >= 2) ? 8 : 0);
                    int ng = n0 + wn + ni * 8 + (lane & 3) * 2 + (e & 1);
                    float val = 0.f;
                    if (m < M && ng < Nseg) {
                        val = __expf(acc[mi][ni][e] * alpha);
                        long off = (long)m * ldc1 + ng;
                        __nv_bfloat16 hi, lo; bsplit(val, hi, lo);
                        Cs[off] = hi; Cs[spC + off] = lo;
                    }
                    rp[mi][e >> 1] += val;
                }
#pragma unroll
        for (int mi = 0; mi < MFRAG; mi++)
#pragma unroll
            for (int hh = 0; hh < 2; hh++) {
                float v = rp[mi][hh];
                v += __shfl_xor_sync(0xffffffffu, v, 1);
                v += __shfl_xor_sync(0xffffffffu, v, 2);
                if ((lane & 3) == 0) {
                    int rr = m0 + wm + mi * 16 + (lane >> 2) + hh * 8;
                    if (rr < M) atomicAdd(&rsum[(long)b * (NHEAD * AHORIZ) + rr], v);
                }
            }
    } else {
#pragma unroll
        for (int mi = 0; mi < MFRAG; mi++)
#pragma unroll
            for (int ni = 0; ni < 4; ni++)
#pragma unroll
                for (int e = 0; e < 4; e++) {
                    int m = m0 + wm + mi * 16 + (lane >> 2) + ((e >= 2) ? 8 : 0);
                    int n = wn + ni * 8 + (lane & 3) * 2 + (e & 1);
                    int ng = n0 + n;
                    if (m < M && ng < Nseg) {
                        float v = acc[mi][ni][e];
                        long off;
                        if (rm == 0) off = (long)m * ldc + ng;
                        else if (rm == 1) {  // q head-major: [b][h][s][d]
                            int bq = m / AHORIZ, s = m - bq * AHORIZ;
                            int hh = ng >> 8, d = ng & 255;
                            off = (((long)(bq * NHEAD + hh) * AHORIZ + s) << 8) + d;
                        } else {  // att: rows h*50+s -> [s][h][d]
                            int hh = m / AHORIZ, s = m - hh * AHORIZ;
                            off = (long)s * (NHEAD * HD) + hh * HD + ng;
                        }
                        switch (ep) {
                            case EP_NONE: C[off] = v; break;
                            case EP_BIAS: C[off] = v + aux[ng]; break;
                            case EP_BIAS_SILU: { float x = v + aux[ng];
                                C[off] = x * __fdividef(1.f, 1.f + __expf(-x)); } break;
                            case EP_BIAS_SCALE: C[off] = (v + aux[ng]) * alpha; break;
                            case EP_ACC: atomicAdd(&C[off], v); break;
                            case EP_SCALE: C[off] = v * alpha; break;
                            case EP_SPLIT: {
                                __nv_bfloat16 hi, lo; bsplit(v, hi, lo);
                                Cs[off] = hi; Cs[spC + off] = lo;
                            } break;
                            case EP_DIVSPLIT: {
                                v *= __fdividef(1.f, rsum[(long)b * (NHEAD * AHORIZ) + m]);
                                __nv_bfloat16 hi, lo; bsplit(v, hi, lo);
                                Cs[off] = hi; Cs[spC + off] = lo;
                            } break;
                        }
                    }
                }
    }
#undef SA
#undef SB
}

// ================= dual-B fused up+gate+GEGLU GEMM =================
__global__ void __launch_bounds__(256, 2) mma_gemm_geglu(
    const __nv_bfloat16* __restrict__ A, long lda, long spA,
    const float* __restrict__ B1, const float* __restrict__ B2, long ldb,
    __nv_bfloat16* __restrict__ Csp, long ldc, long spC,
    int M, int K)
{
    extern __shared__ __nv_bfloat16 sm[];
    __nv_bfloat16* sAb_ = sm;
    __nv_bfloat16* sBb_ = sm + 4 * 64 * ASTR;
#define SA2(st, pl, m) (sAb_ + (((st) * 2 + (pl)) * 64 + (m)) * ASTR)
#define SB2(st, mat, pl, k) (sBb_ + ((((st) * 2 + (mat)) * 2 + (pl)) * 32 + (k)) * BSTR)

    int tid = threadIdx.x;
    int m0 = blockIdx.y * 64;
    int n0 = blockIdx.x * 64;
    int warp = tid >> 5, lane = tid & 31;
    int wm = (warp >> 1) * 16, wn = (warp & 1) * 32;

    float accU[4][4], accG[4][4];
#pragma unroll
    for (int ni = 0; ni < 4; ni++)
#pragma unroll
        for (int e = 0; e < 4; e++) { accU[ni][e] = 0.f; accG[ni][e] = 0.f; }

    int arow = tid >> 2, ak = (tid & 3) * 8;
    int bkr = tid >> 3, bn8 = (tid & 7) * 8;

    uint4 rahi0, ralo0, rahi1, ralo1;
    float4 ru00, ru01, rg00, rg01, ru10, ru11, rg10, rg11;

    auto loadA = [&](int k0, uint4& rahi, uint4& ralo) {
        int m = m0 + arow;
        if (m < M) {
            const __nv_bfloat16* src = A + (long)m * lda + k0 + ak;
            rahi = *(const uint4*)src;
            ralo = *(const uint4*)(src + spA);
        } else {
            rahi = make_uint4(0, 0, 0, 0); ralo = make_uint4(0, 0, 0, 0);
        }
    };
    auto loadB = [&](int k0, float4& ru0, float4& ru1, float4& rg0, float4& rg1) {
        const float* s1 = B1 + (long)(k0 + bkr) * ldb + n0 + bn8;
        const float* s2 = B2 + (long)(k0 + bkr) * ldb + n0 + bn8;
        ru0 = *(const float4*)s1; ru1 = *(const float4*)(s1 + 4);
        rg0 = *(const float4*)s2; rg1 = *(const float4*)(s2 + 4);
    };
    auto storeTiles = [&](int st, uint4& rahi, uint4& ralo,
                          float4& ru0, float4& ru1, float4& rg0, float4& rg1) {
        *(uint4*)(SA2(st, 0, arow) + ak) = rahi;
        *(uint4*)(SA2(st, 1, arow) + ak) = ralo;
        float uv[8] = {ru0.x, ru0.y, ru0.z, ru0.w, ru1.x, ru1.y, ru1.z, ru1.w};
        float gv[8] = {rg0.x, rg0.y, rg0.z, rg0.w, rg1.x, rg1.y, rg1.z, rg1.w};
        uint32_t h4[4], l4[4];
#pragma unroll
        for (int j = 0; j < 4; j++) bsplit2(uv[2 * j], uv[2 * j + 1], h4[j], l4[j]);
        *(uint4*)(SB2(st, 0, 0, bkr) + bn8) = make_uint4(h4[0], h4[1], h4[2], h4[3]);
        *(uint4*)(SB2(st, 0, 1, bkr) + bn8) = make_uint4(l4[0], l4[1], l4[2], l4[3]);
#pragma unroll
        for (int j = 0; j < 4; j++) bsplit2(gv[2 * j], gv[2 * j + 1], h4[j], l4[j]);
        *(uint4*)(SB2(st, 1, 0, bkr) + bn8) = make_uint4(h4[0], h4[1], h4[2], h4[3]);
        *(uint4*)(SB2(st, 1, 1, bkr) + bn8) = make_uint4(l4[0], l4[1], l4[2], l4[3]);
    };

    int r = lane & 15, cg = lane >> 4;

    auto compute = [&](int st) {
#pragma unroll
        for (int kh = 0; kh < 2; kh++) {
            uint32_t ah[4], al[4];
            ldsm4(ah, s2u(SA2(st, 0, wm + r) + kh * 16 + cg * 8));
            ldsm4(al, s2u(SA2(st, 1, wm + r) + kh * 16 + cg * 8));
#pragma unroll
            for (int mat = 0; mat < 2; mat++) {
                uint32_t bhf[8], blf[8];
#pragma unroll
                for (int g = 0; g < 2; g++) {
                    ldsm4t(&bhf[g * 4], s2u(SB2(st, mat, 0, kh * 16 + r) + wn + g * 16 + cg * 8));
                    ldsm4t(&blf[g * 4], s2u(SB2(st, mat, 1, kh * 16 + r) + wn + g * 16 + cg * 8));
                }
                float (*acc)[4] = mat ? accG : accU;
#pragma unroll
                for (int ni = 0; ni < 4; ni++) {
                    mma16816(acc[ni], ah, &bhf[ni * 2]);
                    mma16816(acc[ni], ah, &blf[ni * 2]);
                    mma16816(acc[ni], al, &bhf[ni * 2]);
                }
            }
        }
    };

    loadA(0, rahi0, ralo0); loadB(0, ru00, ru01, rg00, rg01);
    if (32 < K) { loadA(32, rahi1, ralo1); loadB(32, ru10, ru11, rg10, rg11); }

    for (int k0 = 0; k0 < K; k0 += 64) {
        storeTiles(0, rahi0, ralo0, ru00, ru01, rg00, rg01);
        __syncthreads();
        if (k0 + 64 < K) { loadA(k0 + 64, rahi0, ralo0); loadB(k0 + 64, ru00, ru01, rg00, rg01); }
        compute(0);
        if (k0 + 32 >= K) break;
        storeTiles(1, rahi1, ralo1, ru10, ru11, rg10, rg11);
        __syncthreads();
        if (k0 + 96 < K) { loadA(k0 + 96, rahi1, ralo1); loadB(k0 + 96, ru10, ru11, rg10, rg11); }
        compute(1);
    }

#pragma unroll
    for (int ni = 0; ni < 4; ni++)
#pragma unroll
        for (int e = 0; e < 4; e++) {
            int m = m0 + wm + (lane >> 2) + ((e >= 2) ? 8 : 0);
            int ng = n0 + wn + ni * 8 + (lane & 3) * 2 + (e & 1);
            if (m < M) {
                float o = fast_gelu(accG[ni][e]) * accU[ni][e];
                long off = (long)m * ldc + ng;
                __nv_bfloat16 hi, lo; bsplit(o, hi, lo);
                Csp[off] = hi; Csp[spC + off] = lo;
            }
        }
#undef SA2
#undef SB2
}

// ================= time embedding =================
__global__ void time_emb_kernel(const float* __restrict__ ts, float* __restrict__ emb) {
    int b = blockIdx.x;
    int i = threadIdx.x;
    float frac = (float)i / 511.f;
    float period = 0.004f * __expf(frac * 6.907755278982137f);
    float w = 6.283185307179586f / period;
    float si = w * ts[b];
    float s, c;
    sincosf(si, &s, &c);
    emb[b * WIDTH + i] = s;
    emb[b * WIDTH + 512 + i] = c;
}

// ================= adaRMS scale precompute =================
__global__ void condinit_kernel(const float* __restrict__ ln1_w, const float* __restrict__ ln2_w,
                                const float* __restrict__ fin_w,
                                float* __restrict__ s1, float* __restrict__ s2,
                                float* __restrict__ fs) {
    int idx = blockIdx.x * 256 + threadIdx.x;
    if (idx >= (2 * NLAYER + 1) * WIDTH) return;
    int slab = idx >> 10, c = idx & 1023;
    const float* w;
    float* out;
    if (slab < NLAYER) { w = ln1_w + slab * WIDTH; out = s1 + (long)slab * NB * WIDTH; }
    else if (slab < 2 * NLAYER) { int l = slab - NLAYER; w = ln2_w + l * WIDTH; out = s2 + (long)l * NB * WIDTH; }
    else { w = fin_w; out = fs; }
    float base = 1.f + w[c];
#pragma unroll
    for (int b = 0; b < NB; b++) out[b * WIDTH + c] = base;
}

__global__ void condacc_kernel(const float* __restrict__ cond,
                               const float* __restrict__ ln1_ada, const float* __restrict__ ln2_ada,
                               const float* __restrict__ fin_ada,
                               float* __restrict__ s1, float* __restrict__ s2,
                               float* __restrict__ fs) {
    int slab = blockIdx.y;
    int ks = blockIdx.x;
    const float* ada;
    float* out;
    if (slab < NLAYER) { ada = ln1_ada + (long)slab * WIDTH * WIDTH; out = s1 + (long)slab * NB * WIDTH; }
    else if (slab < 2 * NLAYER) { int l = slab - NLAYER; ada = ln2_ada + (long)l * WIDTH * WIDTH; out = s2 + (long)l * NB * WIDTH; }
    else { ada = fin_ada; out = fs; }
    int kbeg = ks * 128;
    __shared__ float sc[NB][128];
    for (int i = threadIdx.x; i < NB * 128; i += 512)
        sc[i >> 7][i & 127] = cond[(i >> 7) * WIDTH + kbeg + (i & 127)];
    __syncthreads();
    int c2 = threadIdx.x;
    float a[NB][2];
#pragma unroll
    for (int b = 0; b < NB; b++) { a[b][0] = 0.f; a[b][1] = 0.f; }
#pragma unroll 4
    for (int kk = 0; kk < 128; kk++) {
        float2 wv = *(const float2*)(ada + (long)(kbeg + kk) * WIDTH + c2 * 2);
#pragma unroll
        for (int b = 0; b < NB; b++) {
            float cv = sc[b][kk];
            a[b][0] += cv * wv.x; a[b][1] += cv * wv.y;
        }
    }
#pragma unroll
    for (int b = 0; b < NB; b++) {
        atomicAdd(&out[b * WIDTH + c2 * 2], a[b][0]);
        atomicAdd(&out[b * WIDTH + c2 * 2 + 1], a[b][1]);
    }
}

// ================= adaptive RMSNorm -> split bf16 planes =================
__global__ void adarms_kernel(const float* __restrict__ x, const float* __restrict__ scale,
                              __nv_bfloat16* __restrict__ osp) {
    int row = blockIdx.x;
    int b = row / AHORIZ;
    const float* xr = x + (long)row * WIDTH;
    __shared__ float red[256];
    int tid = threadIdx.x;
    float ss = 0.f;
    for (int c = tid; c < WIDTH; c += 256) { float v = xr[c]; ss += v * v; }
    red[tid] = ss;
    __syncthreads();
    for (int s2 = 128; s2 > 0; s2 >>= 1) {
        if (tid < s2) red[tid] += red[tid + s2];
        __syncthreads();
    }
    float inv = rsqrtf(red[0] / (float)WIDTH + 1e-6f);
    const float* sr = scale + (long)b * WIDTH;
    __nv_bfloat16* ohi = osp + (long)row * WIDTH;
    for (int c = tid; c < WIDTH; c += 256) {
        float v = xr[c] * inv * sr[c];
        __nv_bfloat16 hi, lo; bsplit(v, hi, lo);
        ohi[c] = hi; ohi[SP_N + c] = lo;
    }
}

// ================= RoPE: q (fp32 in, split out) + k (fp32 in-place) + rsum zero ========
__global__ void rope_both_kernel(const float* __restrict__ q, float* __restrict__ k,
                                 __nv_bfloat16* __restrict__ qsp, float* __restrict__ rsum) {
    int idx = blockIdx.x * blockDim.x + threadIdx.x;
    if (idx < NB * NHEAD * AHORIZ) rsum[idx] = 0.f;
    int total = (NB * NHEAD * AHORIZ + NROWS) * 128;
    if (idx >= total) return;
    int i = idx & 127;
    int rr = idx >> 7;
    float inv = __expf(-(float)i * 0.0719544577297821f);
    if (rr < NB * NHEAD * AHORIZ) {
        int s = rr % AHORIZ;
        float fr = (float)(PREF + s) * inv;
        float c, sn;
        sincosf(fr, &sn, &c);
        const float* base = q + (long)rr * HD;
        float x1 = base[i], x2 = base[i + 128];
        float y1 = x1 * c - x2 * sn, y2 = x2 * c + x1 * sn;
        __nv_bfloat16 h1, l1, h2, l2;
        bsplit(y1, h1, l1); bsplit(y2, h2, l2);
        __nv_bfloat16* dst = qsp + (long)rr * HD;
        dst[i] = h1; dst[i + 128] = h2;
        dst[SP_Q + i] = l1; dst[SP_Q + i + 128] = l2;
    } else {
        int rk = rr - NB * NHEAD * AHORIZ;
        int s = rk % AHORIZ;
        float fr = (float)(PREF + s) * inv;
        float c, sn;
        sincosf(fr, &sn, &c);
        float* base = k + (long)rk * HD;
        float x1 = base[i], x2 = base[i + 128];
        base[i] = x1 * c - x2 * sn;
        base[i + 128] = x2 * c + x1 * sn;
    }
}

// ================= host driver =================
#define SMEM_128 (4 * 128 * ASTR * 2 + 4 * 32 * BSTR * 2)
#define SMEM_64  (4 * 64 * ASTR * 2 + 4 * 32 * BSTR * 2)
#define SMEM_GG  (4 * 64 * ASTR * 2 + 8 * 32 * BSTR * 2)

extern "C" void kernel_launch(void* const* d_in, const int* in_sizes, int n_in,
                              void* d_out, int out_size) {
    (void)in_sizes; (void)n_in; (void)out_size;
    const float* past_keys   = (const float*)d_in[1];
    const float* past_values = (const float*)d_in[2];
    const float* x_t         = (const float*)d_in[3];
    const float* timestep    = (const float*)d_in[4];
    const float* w_act_in    = (const float*)d_in[5];
    const float* b_act_in    = (const float*)d_in[6];
    const float* w_tin       = (const float*)d_in[7];
    const float* b_tin       = (const float*)d_in[8];
    const float* w_tout      = (const float*)d_in[9];
    const float* b_tout      = (const float*)d_in[10];
    const float* w_act_out   = (const float*)d_in[11];
    const float* b_act_out   = (const float*)d_in[12];
    const float* wq          = (const float*)d_in[13];
    const float* wk          = (const float*)d_in[14];
    const float* wv          = (const float*)d_in[15];
    const float* wo          = (const float*)d_in[16];
    const float* w_gate      = (const float*)d_in[17];
    const float* w_up        = (const float*)d_in[18];
    const float* w_down      = (const float*)d_in[19];
    const float* ln1_w       = (const float*)d_in[20];
    const float* ln1_ada     = (const float*)d_in[21];
    const float* ln2_w       = (const float*)d_in[22];
    const float* ln2_ada     = (const float*)d_in[23];
    const float* fin_w       = (const float*)d_in[24];
    const float* fin_ada     = (const float*)d_in[25];
    float* out = (float*)d_out;

    cudaFuncSetAttribute(mma_gemm<128, true>, cudaFuncAttributeMaxDynamicSharedMemorySize, SMEM_128);
    cudaFuncSetAttribute(mma_gemm<64, true>, cudaFuncAttributeMaxDynamicSharedMemorySize, SMEM_64);
    cudaFuncSetAttribute(mma_gemm<64, false>, cudaFuncAttributeMaxDynamicSharedMemorySize, SMEM_64);
    cudaFuncSetAttribute(mma_gemm_geglu, cudaFuncAttributeMaxDynamicSharedMemorySize, SMEM_GG);

    float *p_time, *p_t1, *p_cond, *p_s1, *p_s2, *p_fs, *p_h, *p_q, *p_k, *p_v, *p_rsum;
    __nv_bfloat16 *p_nsp, *p_qsp, *p_psp, *p_attsp, *p_actsp;
    cudaGetSymbolAddress((void**)&p_time, g_time_emb);
    cudaGetSymbolAddress((void**)&p_t1, g_t1);
    cudaGetSymbolAddress((void**)&p_cond, g_cond);
    cudaGetSymbolAddress((void**)&p_s1, g_scale1);
    cudaGetSymbolAddress((void**)&p_s2, g_scale2);
    cudaGetSymbolAddress((void**)&p_fs, g_fscale);
    cudaGetSymbolAddress((void**)&p_h, g_h);
    cudaGetSymbolAddress((void**)&p_q, g_q);
    cudaGetSymbolAddress((void**)&p_k, g_k);
    cudaGetSymbolAddress((void**)&p_v, g_v);
    cudaGetSymbolAddress((void**)&p_rsum, g_rsum);
    cudaGetSymbolAddress((void**)&p_nsp, g_nsp);
    cudaGetSymbolAddress((void**)&p_qsp, g_qsp);
    cudaGetSymbolAddress((void**)&p_psp, g_psp);
    cudaGetSymbolAddress((void**)&p_attsp, g_attsp);
    cudaGetSymbolAddress((void**)&p_actsp, g_actsp);

    auto gemm64f = [&](const float* A, long lda, const float* B, long ldb,
                       float* C, long ldc, int M, int N, int K,
                       const float* aux, int ep, float alpha) {
        dim3 g((N + 63) / 64, (M + 63) / 64, 1);
        mma_gemm<64, false><<<g, 256, SMEM_64>>>(
            A, lda, 0, 0, B, ldb, 0, 0, 0, 0, 0, 0,
            C, ldc, 0, 0, 0, 0, 0, 0, 0, 0,
            M, K, 1, 0, BMODE_NORMAL,
            1 << 30, 1 << 30, N, 0, 0, aux, ep, alpha, 0);
    };
    auto gemm128s = [&](const __nv_bfloat16* A, long lda, long spA,
                        const float* B, long ldb,
                        float* C, long ldc, int M, int N, int K, int nk,
                        const float* aux, int ep, float alpha) {
        dim3 g((N + 63) / 64, (M + 127) / 128, nk);
        mma_gemm<128, true><<<g, 256, SMEM_128>>>(
            A, lda, 0, spA, B, ldb, 0, 0, 0, 0, 0, 0,
            C, ldc, 0, 0, 0, 0, 0, 0, 0, 0,
            M, K, nk, 0, BMODE_NORMAL,
            1 << 30, 1 << 30, N, 0, 0, aux, ep, alpha, 0);
    };

    // --- prologue ---
    time_emb_kernel<<<NB, 512>>>(timestep, p_time);
    gemm64f(p_time, WIDTH, w_tin, WIDTH, p_t1, WIDTH, NB, WIDTH, WIDTH, b_tin, EP_BIAS_SILU, 0.f);
    gemm64f(p_t1, WIDTH, w_tout, WIDTH, p_cond, WIDTH, NB, WIDTH, WIDTH, b_tout, EP_BIAS_SILU, 0.f);
    condinit_kernel<<<((2 * NLAYER + 1) * WIDTH + 255) / 256, 256>>>(ln1_w, ln2_w, fin_w, p_s1, p_s2, p_fs);
    condacc_kernel<<<dim3(8, 2 * NLAYER + 1), 512>>>(p_cond, ln1_ada, ln2_ada, fin_ada, p_s1, p_s2, p_fs);
    gemm64f(x_t, ADIM, w_act_in, WIDTH, p_h, WIDTH, NROWS, WIDTH, ADIM, b_act_in, EP_BIAS_SCALE, 32.f);

    for (int l = 0; l < NLAYER; l++) {
        const float* kpref = past_keys + (long)l * NB * PREF * HD;
        const float* vpref = past_values + (long)l * NB * PREF * HD;
        const float* wq_l = wq + (long)l * WIDTH * NHEAD * HD;
        const float* wk_l = wk + (long)l * WIDTH * HD;
        const float* wv_l = wv + (long)l * WIDTH * HD;
        const float* wo_l = wo + (long)l * NHEAD * HD * WIDTH;
        const float* wg_l = w_gate + (long)l * WIDTH * MLPD;
        const float* wu_l = w_up + (long)l * WIDTH * MLPD;
        const float* wd_l = w_down + (long)l * MLPD * WIDTH;

        adarms_kernel<<<NROWS, 256>>>(p_h, p_s1 + (long)l * NB * WIDTH, p_nsp);

        // fused QKV (BM=64): x [0,32)->q (remap), [32,36)->k, [36,40)->v
        {
            dim3 g(40, 4, 1);
            mma_gemm<64, true><<<g, 256, SMEM_64>>>(
                p_nsp, WIDTH, 0, SP_N,
                wq_l, NHEAD * HD, 0, wk_l, HD, 0, wv_l, HD,
                p_q, 0, p_k, HD, p_v, HD, 0, 0, 0, 0,
                NROWS, WIDTH, 1, 0, BMODE_NORMAL,
                32, 36, NHEAD * HD, HD, HD, 0, EP_NONE, 0.f, 1);
        }

        rope_both_kernel<<<((NB * NHEAD * AHORIZ + NROWS) * 128 + 255) / 256, 256>>>(
            p_q, p_k, p_qsp, p_rsum);

        // scores + exp + split-write psp + row sums (fused softmax): per-b M=400, BM=64
        {
            dim3 g((TOT + 63) / 64, 7, NB);
            mma_gemm<64, true><<<g, 256, SMEM_64>>>(
                p_qsp, HD, (long)NHEAD * AHORIZ * HD, SP_Q,
                kpref, HD, (long)PREF * HD,
                p_k, HD, (long)AHORIZ * HD, 0, 0,
                0, 1024, 0, 0, 0, 0,
                (long)NHEAD * AHORIZ * 1024, p_psp, SP_P, p_rsum,
                NHEAD * AHORIZ, HD, 1, TOT, BMODE_TRANS_SEG,
                1 << 30, 1 << 30, TOT, 0, 0, 0, EP_EXPSPLITSUM, 0.0625f, 0);
        }

        // PV (BM=64, APRE from psp): epilogue divides by rowsum, splits att [s][h][d]
        {
            dim3 g(HD / 64, 7, NB);
            mma_gemm<64, true><<<g, 256, SMEM_64>>>(
                p_psp, 1024, (long)NHEAD * AHORIZ * 1024, SP_P,
                vpref, HD, (long)PREF * HD,
                p_v, HD, (long)AHORIZ * HD, 0, 0,
                0, 0, 0, 0, 0, 0,
                (long)AHORIZ * NHEAD * HD, p_attsp, SP_ATT, p_rsum,
                NHEAD * AHORIZ, 1024, 1, TOT, BMODE_SEG,
                1 << 30, 1 << 30, HD, 0, 0, 0, EP_DIVSPLIT, 0.f, 2);
        }

        // output proj, split-K=4, accumulate into h
        gemm128s(p_attsp, NHEAD * HD, SP_ATT, wo_l, WIDTH, p_h, WIDTH,
                 NROWS, WIDTH, NHEAD * HD, 4, 0, EP_ACC, 0.f);

        adarms_kernel<<<NROWS, 256>>>(p_h, p_s2 + (long)l * NB * WIDTH, p_nsp);

        // fused up+gate+GEGLU: actsp = split(gelu(A@wg) * (A@wu))
        {
            dim3 g(MLPD / 64, 4, 1);
            mma_gemm_geglu<<<g, 256, SMEM_GG>>>(
                p_nsp, WIDTH, SP_N,
                wu_l, wg_l, MLPD,
                p_actsp, MLPD, SP_ACT,
                NROWS, WIDTH);
        }

        // down proj, split-K=4, accumulate into h
        gemm128s(p_actsp, MLPD, SP_ACT, wd_l, WIDTH, p_h, WIDTH,
                 NROWS, WIDTH, MLPD, 4, 0, EP_ACC, 0.f);
    }

    adarms_kernel<<<NROWS, 256>>>(p_h, p_fs, p_nsp);
    {
        dim3 g(1, (NROWS + 63) / 64, 1);
        mma_gemm<64, true><<<g, 256, SMEM_64>>>(
            p_nsp, WIDTH, 0, SP_N,
            w_act_out, ADIM, 0, 0, 0, 0, 0, 0,
            out, ADIM, 0, 0, 0, 0, 0, 0, 0, 0,
            NROWS, WIDTH, 1, 0, BMODE_NORMAL,
            1 << 30, 1 << 30, ADIM, 0, 0, b_act_out, EP_BIAS, 0.f, 0);
    }
}

// round 17
// speedup vs baseline: 1.0399x; 1.0399x over previous
#include <cuda_runtime.h>
#include <cuda_bf16.h>
#include <math.h>
#include <stdint.h>

// ---------------- problem constants ----------------
#define NLAYER 18
#define WIDTH  1024
#define NHEAD  8
#define HD     256
#define MLPD   4096
#define AHORIZ 50
#define ADIM   32
#define NB     4
#define PREF   968
#define TOT    (PREF + AHORIZ)   // 1018
#define NROWS  (NB * AHORIZ)     // 200

enum { EP_NONE = 0, EP_BIAS, EP_BIAS_SILU, EP_BIAS_SCALE, EP_ACC, EP_SCALE, EP_SPLIT };
enum { BMODE_NORMAL = 0, BMODE_TRANS_SEG = 1, BMODE_SEG = 2 };

// ---------------- device scratch ----------------
__device__ float g_time_emb[NB * WIDTH];
__device__ float g_t1[NB * WIDTH];
__device__ float g_cond[NB * WIDTH];
__device__ float g_scale1[NLAYER * NB * WIDTH];
__device__ float g_scale2[NLAYER * NB * WIDTH];
__device__ float g_fscale[NB * WIDTH];
__device__ float g_h[NROWS * WIDTH];
__device__ float g_q[NB * NHEAD * AHORIZ * HD];   // [b][h][s][d] fp32 (pre-rope)
__device__ float g_k[NROWS * HD];
__device__ float g_v[NROWS * HD];
__device__ float g_scores[NB * NHEAD * AHORIZ * 1024];

// pre-split bf16 operand planes [2][...]
__device__ __nv_bfloat16 g_nsp[2 * NROWS * WIDTH];
__device__ __nv_bfloat16 g_qsp[2 * NB * NHEAD * AHORIZ * HD];
__device__ __nv_bfloat16 g_psp[2 * NB * NHEAD * AHORIZ * 1024];
__device__ __nv_bfloat16 g_attsp[2 * NROWS * NHEAD * HD];
__device__ __nv_bfloat16 g_actsp[2 * NROWS * MLPD];

#define SP_N   (NROWS * WIDTH)
#define SP_Q   (NB * NHEAD * AHORIZ * HD)
#define SP_P   (NB * NHEAD * AHORIZ * 1024)
#define SP_ATT (NROWS * NHEAD * HD)
#define SP_ACT (NROWS * MLPD)

__device__ __forceinline__ float fast_gelu(float x) {
    float u = 0.7978845608028654f * (x + 0.044715f * x * x * x);
    float e = __expf(2.f * u);
    float t = 1.f - __fdividef(2.f, e + 1.f);
    return 0.5f * x * (1.f + t);
}

__device__ __forceinline__ uint32_t s2u(const void* p) {
    return (uint32_t)__cvta_generic_to_shared(p);
}
__device__ __forceinline__ void ldsm4(uint32_t* r, uint32_t addr) {
    asm volatile("ldmatrix.sync.aligned.m8n8.x4.shared.b16 {%0,%1,%2,%3}, [%4];"
                 : "=r"(r[0]), "=r"(r[1]), "=r"(r[2]), "=r"(r[3]) : "r"(addr));
}
__device__ __forceinline__ void ldsm4t(uint32_t* r, uint32_t addr) {
    asm volatile("ldmatrix.sync.aligned.m8n8.x4.trans.shared.b16 {%0,%1,%2,%3}, [%4];"
                 : "=r"(r[0]), "=r"(r[1]), "=r"(r[2]), "=r"(r[3]) : "r"(addr));
}
__device__ __forceinline__ void mma16816(float* c, const uint32_t* a, const uint32_t* b) {
    asm volatile(
        "mma.sync.aligned.m16n8k16.row.col.f32.bf16.bf16.f32 "
        "{%0,%1,%2,%3}, {%4,%5,%6,%7}, {%8,%9}, {%0,%1,%2,%3};"
        : "+f"(c[0]), "+f"(c[1]), "+f"(c[2]), "+f"(c[3])
        : "r"(a[0]), "r"(a[1]), "r"(a[2]), "r"(a[3]), "r"(b[0]), "r"(b[1]));
}
__device__ __forceinline__ void bsplit(float x, __nv_bfloat16& hi, __nv_bfloat16& lo) {
    hi = __float2bfloat16(x);
    lo = __float2bfloat16(x - __bfloat162float(hi));
}
__device__ __forceinline__ void bsplit2(float x0, float x1, uint32_t& hi2, uint32_t& lo2) {
    __nv_bfloat16 h0, l0, h1, l1;
    bsplit(x0, h0, l0); bsplit(x1, h1, l1);
    __nv_bfloat162 hp = __nv_bfloat162(h0, h1), lp = __nv_bfloat162(l0, l1);
    hi2 = *(uint32_t*)&hp; lo2 = *(uint32_t*)&lp;
}

#define ASTR 40
#define BSTR 72

// ================= split-bf16 tensor-core GEMM, BMx64x32 tile, 2-deep prefetch ==========
template <int BM, bool APRE>
__global__ void __launch_bounds__(256, 2) mma_gemm(
    const void* __restrict__ Aptr, long lda, long sAb, long spA,
    const float* __restrict__ B1, long ldb1, long sB1b,
    const float* __restrict__ B2, long ldb2, long sB2b,
    const float* __restrict__ B3, long ldb3,
    float* __restrict__ C1, long ldc1,
    float* __restrict__ C2, long ldc2,
    float* __restrict__ C3, long ldc3,
    long sCb,
    __nv_bfloat16* __restrict__ Csp, long spC,
    int M, int K, int nk, int tmax, int bmode,
    int xs1, int xs2, int N1, int N2, int N3,
    const float* __restrict__ aux, int ep, float alpha, int remap)
{
    constexpr int TPR = 256 / BM;
    constexpr int FPT = 32 / TPR;
    constexpr int NV4 = FPT / 8;
    constexpr int MFRAG = BM / 64;

    int z = blockIdx.z;
    int ks = z % nk, b = z / nk;

    const float* Af = (const float*)Aptr + (long)b * sAb;
    const __nv_bfloat16* Abf = (const __nv_bfloat16*)Aptr + (long)b * sAb;
    const float* Bp1 = B1 + (long)b * sB1b;
    const float* Bp2 = B2 ? B2 + (long)b * sB2b : (const float*)0;

    const float* B = Bp1;
    float* C = C1;
    long ldb = ldb1, ldc = ldc1;
    int n0, Nseg = N1;
    int xb = blockIdx.x;
    int rm = remap;
    if (bmode == BMODE_NORMAL) {
        if (xb < xs1) { n0 = xb * 64; }
        else if (xb < xs2) { B = B2; C = C2; ldb = ldb2; ldc = ldc2; Nseg = N2; n0 = (xb - xs1) * 64; rm = 0; }
        else { B = B3; C = C3; ldb = ldb3; ldc = ldc3; Nseg = N3; n0 = (xb - xs2) * 64; rm = 0; }
    } else {
        n0 = xb * 64;
    }
    C += (long)b * sCb;
    __nv_bfloat16* Cs = Csp ? Csp + (long)b * sCb : (__nv_bfloat16*)0;

    extern __shared__ __nv_bfloat16 sm[];
    __nv_bfloat16* sAb_ = sm;
    __nv_bfloat16* sBb_ = sm + 4 * BM * ASTR;
#define SA(st, pl, m) (sAb_ + (((st) * 2 + (pl)) * BM + (m)) * ASTR)
#define SB(st, pl, k) (sBb_ + (((st) * 2 + (pl)) * 32 + (k)) * BSTR)

    int tid = threadIdx.x;
    int m0 = blockIdx.y * BM;
    int warp = tid >> 5, lane = tid & 31;
    int wm = (warp >> 1) * (BM / 4), wn = (warp & 1) * 32;

    float acc[MFRAG][4][4];
#pragma unroll
    for (int mi = 0; mi < MFRAG; mi++)
#pragma unroll
        for (int ni = 0; ni < 4; ni++)
#pragma unroll
            for (int e = 0; e < 4; e++) acc[mi][ni][e] = 0.f;

    const float4 fz = make_float4(0.f, 0.f, 0.f, 0.f);

    int kbeg = ks * (K / nk);
    int kend = kbeg + (K / nk);

    int arow = tid / TPR, ak = (tid % TPR) * FPT;
    int bkr = tid >> 3, bn8 = (tid & 7) * 8;
    int ttl = tid >> 2, tk = (tid & 3) * 8;

    float ra0[APRE ? 1 : FPT], ra1[APRE ? 1 : FPT];
    uint4 rahi0[APRE ? NV4 : 1], ralo0[APRE ? NV4 : 1];
    uint4 rahi1[APRE ? NV4 : 1], ralo1[APRE ? NV4 : 1];
    float4 rb00, rb01, rb10, rb11;

    auto loadA = [&](int k0, uint4* rahi, uint4* ralo, float* ra) {
        int m = m0 + arow;
        if constexpr (APRE) {
            if (m < M) {
                const __nv_bfloat16* src = Abf + (long)m * lda + k0 + ak;
#pragma unroll
                for (int v = 0; v < NV4; v++) {
                    rahi[v] = ((const uint4*)src)[v];
                    ralo[v] = ((const uint4*)(src + spA))[v];
                }
            } else {
                uint4 z4 = make_uint4(0, 0, 0, 0);
#pragma unroll
                for (int v = 0; v < NV4; v++) { rahi[v] = z4; ralo[v] = z4; }
            }
        } else {
            if (m < M) {
                const float* src = Af + (long)m * lda + k0 + ak;
#pragma unroll
                for (int f = 0; f < FPT / 4; f++)
                    *(float4*)(ra + 4 * f) = *(const float4*)(src + 4 * f);
            } else {
#pragma unroll
                for (int f = 0; f < FPT; f++) ra[f] = 0.f;
            }
        }
    };
    auto loadB = [&](int k0, float4& rb0, float4& rb1) {
        if (bmode == BMODE_NORMAL) {
            int n = n0 + bn8;
            if (n < Nseg) {
                const float* src = B + (long)(k0 + bkr) * ldb + n;
                rb0 = *(const float4*)src;
                rb1 = *(const float4*)(src + 4);
            } else { rb0 = fz; rb1 = fz; }
        } else if (bmode == BMODE_TRANS_SEG) {
            int t = n0 + ttl;
            if (t < tmax) {
                const float* src = (t < PREF) ? Bp1 + (long)t * ldb1
                                              : Bp2 + (long)(t - PREF) * ldb1;
                rb0 = *(const float4*)(src + k0 + tk);
                rb1 = *(const float4*)(src + k0 + tk + 4);
            } else { rb0 = fz; rb1 = fz; }
        } else {
            int t = k0 + bkr;
            if (t < tmax) {
                const float* src = (t < PREF) ? Bp1 + (long)t * ldb1
                                              : Bp2 + (long)(t - PREF) * ldb1;
                rb0 = *(const float4*)(src + n0 + bn8);
                rb1 = *(const float4*)(src + n0 + bn8 + 4);
            } else { rb0 = fz; rb1 = fz; }
        }
    };
    auto storeTiles = [&](int st, uint4* rahi, uint4* ralo, float* ra,
                          float4& rb0, float4& rb1) {
        if constexpr (APRE) {
            uint4* dh = (uint4*)(SA(st, 0, arow) + ak);
            uint4* dl = (uint4*)(SA(st, 1, arow) + ak);
#pragma unroll
            for (int v = 0; v < NV4; v++) { dh[v] = rahi[v]; dl[v] = ralo[v]; }
        } else {
            uint32_t* pAh = (uint32_t*)(SA(st, 0, arow) + ak);
            uint32_t* pAl = (uint32_t*)(SA(st, 1, arow) + ak);
#pragma unroll
            for (int j = 0; j < FPT / 2; j++) {
                uint32_t hi2, lo2;
                bsplit2(ra[2 * j], ra[2 * j + 1], hi2, lo2);
                pAh[j] = hi2; pAl[j] = lo2;
            }
        }
        float bv[8] = {rb0.x, rb0.y, rb0.z, rb0.w, rb1.x, rb1.y, rb1.z, rb1.w};
        if (bmode == BMODE_TRANS_SEG) {
#pragma unroll
            for (int j = 0; j < 8; j++) {
                __nv_bfloat16 hi, lo; bsplit(bv[j], hi, lo);
                SB(st, 0, tk + j)[ttl] = hi; SB(st, 1, tk + j)[ttl] = lo;
            }
        } else {
            uint32_t h4[4], l4[4];
#pragma unroll
            for (int j = 0; j < 4; j++) bsplit2(bv[2 * j], bv[2 * j + 1], h4[j], l4[j]);
            *(uint4*)(SB(st, 0, bkr) + bn8) = make_uint4(h4[0], h4[1], h4[2], h4[3]);
            *(uint4*)(SB(st, 1, bkr) + bn8) = make_uint4(l4[0], l4[1], l4[2], l4[3]);
        }
    };

    int r = lane & 15, cg = lane >> 4;

    auto compute = [&](int st) {
#pragma unroll
        for (int kh = 0; kh < 2; kh++) {
            uint32_t bhf[8], blf[8];
#pragma unroll
            for (int g = 0; g < 2; g++) {
                ldsm4t(&bhf[g * 4], s2u(SB(st, 0, kh * 16 + r) + wn + g * 16 + cg * 8));
                ldsm4t(&blf[g * 4], s2u(SB(st, 1, kh * 16 + r) + wn + g * 16 + cg * 8));
            }
#pragma unroll
            for (int mi = 0; mi < MFRAG; mi++) {
                uint32_t ah[4], al[4];
                ldsm4(ah, s2u(SA(st, 0, wm + mi * 16 + r) + kh * 16 + cg * 8));
                ldsm4(al, s2u(SA(st, 1, wm + mi * 16 + r) + kh * 16 + cg * 8));
#pragma unroll
                for (int ni = 0; ni < 4; ni++) {
                    mma16816(acc[mi][ni], ah, &bhf[ni * 2]);
                    mma16816(acc[mi][ni], ah, &blf[ni * 2]);
                    mma16816(acc[mi][ni], al, &bhf[ni * 2]);
                }
            }
        }
    };

    loadA(kbeg, rahi0, ralo0, ra0); loadB(kbeg, rb00, rb01);
    if (kbeg + 32 < kend) { loadA(kbeg + 32, rahi1, ralo1, ra1); loadB(kbeg + 32, rb10, rb11); }

    for (int k0 = kbeg; k0 < kend; k0 += 64) {
        storeTiles(0, rahi0, ralo0, ra0, rb00, rb01);
        __syncthreads();
        if (k0 + 64 < kend) { loadA(k0 + 64, rahi0, ralo0, ra0); loadB(k0 + 64, rb00, rb01); }
        compute(0);
        if (k0 + 32 >= kend) break;
        storeTiles(1, rahi1, ralo1, ra1, rb10, rb11);
        __syncthreads();
        if (k0 + 96 < kend) { loadA(k0 + 96, rahi1, ralo1, ra1); loadB(k0 + 96, rb10, rb11); }
        compute(1);
    }

#pragma unroll
    for (int mi = 0; mi < MFRAG; mi++)
#pragma unroll
        for (int ni = 0; ni < 4; ni++)
#pragma unroll
            for (int e = 0; e < 4; e++) {
                int m = m0 + wm + mi * 16 + (lane >> 2) + ((e >= 2) ? 8 : 0);
                int n = wn + ni * 8 + (lane & 3) * 2 + (e & 1);
                int ng = n0 + n;
                if (m < M && ng < Nseg) {
                    float v = acc[mi][ni][e];
                    long off;
                    if (rm == 0) off = (long)m * ldc + ng;
                    else if (rm == 1) {  // q head-major: [b][h][s][d]
                        int bq = m / AHORIZ, s = m - bq * AHORIZ;
                        int hh = ng >> 8, d = ng & 255;
                        off = (((long)(bq * NHEAD + hh) * AHORIZ + s) << 8) + d;
                    } else {  // att: rows h*50+s -> [s][h][d]
                        int hh = m / AHORIZ, s = m - hh * AHORIZ;
                        off = (long)s * (NHEAD * HD) + hh * HD + ng;
                    }
                    switch (ep) {
                        case EP_NONE: C[off] = v; break;
                        case EP_BIAS: C[off] = v + aux[ng]; break;
                        case EP_BIAS_SILU: { float x = v + aux[ng];
                            C[off] = x * __fdividef(1.f, 1.f + __expf(-x)); } break;
                        case EP_BIAS_SCALE: C[off] = (v + aux[ng]) * alpha; break;
                        case EP_ACC: atomicAdd(&C[off], v); break;
                        case EP_SCALE: C[off] = v * alpha; break;
                        case EP_SPLIT: {
                            __nv_bfloat16 hi, lo; bsplit(v, hi, lo);
                            Cs[off] = hi; Cs[spC + off] = lo;
                        } break;
                    }
                }
            }
#undef SA
#undef SB
}

// ================= dual-B fused up+gate+GEGLU GEMM =================
__global__ void __launch_bounds__(256, 2) mma_gemm_geglu(
    const __nv_bfloat16* __restrict__ A, long lda, long spA,
    const float* __restrict__ B1, const float* __restrict__ B2, long ldb,
    __nv_bfloat16* __restrict__ Csp, long ldc, long spC,
    int M, int K)
{
    extern __shared__ __nv_bfloat16 sm[];
    __nv_bfloat16* sAb_ = sm;
    __nv_bfloat16* sBb_ = sm + 4 * 64 * ASTR;
#define SA2(st, pl, m) (sAb_ + (((st) * 2 + (pl)) * 64 + (m)) * ASTR)
#define SB2(st, mat, pl, k) (sBb_ + ((((st) * 2 + (mat)) * 2 + (pl)) * 32 + (k)) * BSTR)

    int tid = threadIdx.x;
    int m0 = blockIdx.y * 64;
    int n0 = blockIdx.x * 64;
    int warp = tid >> 5, lane = tid & 31;
    int wm = (warp >> 1) * 16, wn = (warp & 1) * 32;

    float accU[4][4], accG[4][4];
#pragma unroll
    for (int ni = 0; ni < 4; ni++)
#pragma unroll
        for (int e = 0; e < 4; e++) { accU[ni][e] = 0.f; accG[ni][e] = 0.f; }

    int arow = tid >> 2, ak = (tid & 3) * 8;
    int bkr = tid >> 3, bn8 = (tid & 7) * 8;

    uint4 rahi0, ralo0, rahi1, ralo1;
    float4 ru00, ru01, rg00, rg01, ru10, ru11, rg10, rg11;

    auto loadA = [&](int k0, uint4& rahi, uint4& ralo) {
        int m = m0 + arow;
        if (m < M) {
            const __nv_bfloat16* src = A + (long)m * lda + k0 + ak;
            rahi = *(const uint4*)src;
            ralo = *(const uint4*)(src + spA);
        } else {
            rahi = make_uint4(0, 0, 0, 0); ralo = make_uint4(0, 0, 0, 0);
        }
    };
    auto loadB = [&](int k0, float4& ru0, float4& ru1, float4& rg0, float4& rg1) {
        const float* s1 = B1 + (long)(k0 + bkr) * ldb + n0 + bn8;
        const float* s2 = B2 + (long)(k0 + bkr) * ldb + n0 + bn8;
        ru0 = *(const float4*)s1; ru1 = *(const float4*)(s1 + 4);
        rg0 = *(const float4*)s2; rg1 = *(const float4*)(s2 + 4);
    };
    auto storeTiles = [&](int st, uint4& rahi, uint4& ralo,
                          float4& ru0, float4& ru1, float4& rg0, float4& rg1) {
        *(uint4*)(SA2(st, 0, arow) + ak) = rahi;
        *(uint4*)(SA2(st, 1, arow) + ak) = ralo;
        float uv[8] = {ru0.x, ru0.y, ru0.z, ru0.w, ru1.x, ru1.y, ru1.z, ru1.w};
        float gv[8] = {rg0.x, rg0.y, rg0.z, rg0.w, rg1.x, rg1.y, rg1.z, rg1.w};
        uint32_t h4[4], l4[4];
#pragma unroll
        for (int j = 0; j < 4; j++) bsplit2(uv[2 * j], uv[2 * j + 1], h4[j], l4[j]);
        *(uint4*)(SB2(st, 0, 0, bkr) + bn8) = make_uint4(h4[0], h4[1], h4[2], h4[3]);
        *(uint4*)(SB2(st, 0, 1, bkr) + bn8) = make_uint4(l4[0], l4[1], l4[2], l4[3]);
#pragma unroll
        for (int j = 0; j < 4; j++) bsplit2(gv[2 * j], gv[2 * j + 1], h4[j], l4[j]);
        *(uint4*)(SB2(st, 1, 0, bkr) + bn8) = make_uint4(h4[0], h4[1], h4[2], h4[3]);
        *(uint4*)(SB2(st, 1, 1, bkr) + bn8) = make_uint4(l4[0], l4[1], l4[2], l4[3]);
    };

    int r = lane & 15, cg = lane >> 4;

    auto compute = [&](int st) {
#pragma unroll
        for (int kh = 0; kh < 2; kh++) {
            uint32_t ah[4], al[4];
            ldsm4(ah, s2u(SA2(st, 0, wm + r) + kh * 16 + cg * 8));
            ldsm4(al, s2u(SA2(st, 1, wm + r) + kh * 16 + cg * 8));
#pragma unroll
            for (int mat = 0; mat < 2; mat++) {
                uint32_t bhf[8], blf[8];
#pragma unroll
                for (int g = 0; g < 2; g++) {
                    ldsm4t(&bhf[g * 4], s2u(SB2(st, mat, 0, kh * 16 + r) + wn + g * 16 + cg * 8));
                    ldsm4t(&blf[g * 4], s2u(SB2(st, mat, 1, kh * 16 + r) + wn + g * 16 + cg * 8));
                }
                float (*acc)[4] = mat ? accG : accU;
#pragma unroll
                for (int ni = 0; ni < 4; ni++) {
                    mma16816(acc[ni], ah, &bhf[ni * 2]);
                    mma16816(acc[ni], ah, &blf[ni * 2]);
                    mma16816(acc[ni], al, &bhf[ni * 2]);
                }
            }
        }
    };

    loadA(0, rahi0, ralo0); loadB(0, ru00, ru01, rg00, rg01);
    if (32 < K) { loadA(32, rahi1, ralo1); loadB(32, ru10, ru11, rg10, rg11); }

    for (int k0 = 0; k0 < K; k0 += 64) {
        storeTiles(0, rahi0, ralo0, ru00, ru01, rg00, rg01);
        __syncthreads();
        if (k0 + 64 < K) { loadA(k0 + 64, rahi0, ralo0); loadB(k0 + 64, ru00, ru01, rg00, rg01); }
        compute(0);
        if (k0 + 32 >= K) break;
        storeTiles(1, rahi1, ralo1, ru10, ru11, rg10, rg11);
        __syncthreads();
        if (k0 + 96 < K) { loadA(k0 + 96, rahi1, ralo1); loadB(k0 + 96, ru10, ru11, rg10, rg11); }
        compute(1);
    }

#pragma unroll
    for (int ni = 0; ni < 4; ni++)
#pragma unroll
        for (int e = 0; e < 4; e++) {
            int m = m0 + wm + (lane >> 2) + ((e >= 2) ? 8 : 0);
            int ng = n0 + wn + ni * 8 + (lane & 3) * 2 + (e & 1);
            if (m < M) {
                float o = fast_gelu(accG[ni][e]) * accU[ni][e];
                long off = (long)m * ldc + ng;
                __nv_bfloat16 hi, lo; bsplit(o, hi, lo);
                Csp[off] = hi; Csp[spC + off] = lo;
            }
        }
#undef SA2
#undef SB2
}

// ================= time embedding =================
__global__ void time_emb_kernel(const float* __restrict__ ts, float* __restrict__ emb) {
    int b = blockIdx.x;
    int i = threadIdx.x;
    float frac = (float)i / 511.f;
    float period = 0.004f * __expf(frac * 6.907755278982137f);
    float w = 6.283185307179586f / period;
    float si = w * ts[b];
    float s, c;
    sincosf(si, &s, &c);
    emb[b * WIDTH + i] = s;
    emb[b * WIDTH + 512 + i] = c;
}

// ================= adaRMS scale precompute =================
__global__ void condinit_kernel(const float* __restrict__ ln1_w, const float* __restrict__ ln2_w,
                                const float* __restrict__ fin_w,
                                float* __restrict__ s1, float* __restrict__ s2,
                                float* __restrict__ fs) {
    int idx = blockIdx.x * 256 + threadIdx.x;
    if (idx >= (2 * NLAYER + 1) * WIDTH) return;
    int slab = idx >> 10, c = idx & 1023;
    const float* w;
    float* out;
    if (slab < NLAYER) { w = ln1_w + slab * WIDTH; out = s1 + (long)slab * NB * WIDTH; }
    else if (slab < 2 * NLAYER) { int l = slab - NLAYER; w = ln2_w + l * WIDTH; out = s2 + (long)l * NB * WIDTH; }
    else { w = fin_w; out = fs; }
    float base = 1.f + w[c];
#pragma unroll
    for (int b = 0; b < NB; b++) out[b * WIDTH + c] = base;
}

__global__ void condacc_kernel(const float* __restrict__ cond,
                               const float* __restrict__ ln1_ada, const float* __restrict__ ln2_ada,
                               const float* __restrict__ fin_ada,
                               float* __restrict__ s1, float* __restrict__ s2,
                               float* __restrict__ fs) {
    int slab = blockIdx.y;
    int ks = blockIdx.x;
    const float* ada;
    float* out;
    if (slab < NLAYER) { ada = ln1_ada + (long)slab * WIDTH * WIDTH; out = s1 + (long)slab * NB * WIDTH; }
    else if (slab < 2 * NLAYER) { int l = slab - NLAYER; ada = ln2_ada + (long)l * WIDTH * WIDTH; out = s2 + (long)l * NB * WIDTH; }
    else { ada = fin_ada; out = fs; }
    int kbeg = ks * 128;
    __shared__ float sc[NB][128];
    for (int i = threadIdx.x; i < NB * 128; i += 512)
        sc[i >> 7][i & 127] = cond[(i >> 7) * WIDTH + kbeg + (i & 127)];
    __syncthreads();
    int c2 = threadIdx.x;
    float a[NB][2];
#pragma unroll
    for (int b = 0; b < NB; b++) { a[b][0] = 0.f; a[b][1] = 0.f; }
#pragma unroll 4
    for (int kk = 0; kk < 128; kk++) {
        float2 wv = *(const float2*)(ada + (long)(kbeg + kk) * WIDTH + c2 * 2);
#pragma unroll
        for (int b = 0; b < NB; b++) {
            float cv = sc[b][kk];
            a[b][0] += cv * wv.x; a[b][1] += cv * wv.y;
        }
    }
#pragma unroll
    for (int b = 0; b < NB; b++) {
        atomicAdd(&out[b * WIDTH + c2 * 2], a[b][0]);
        atomicAdd(&out[b * WIDTH + c2 * 2 + 1], a[b][1]);
    }
}

// ================= adaptive RMSNorm -> split bf16 planes =================
__global__ void adarms_kernel(const float* __restrict__ x, const float* __restrict__ scale,
                              __nv_bfloat16* __restrict__ osp) {
    int row = blockIdx.x;
    int b = row / AHORIZ;
    const float* xr = x + (long)row * WIDTH;
    __shared__ float red[256];
    int tid = threadIdx.x;
    float ss = 0.f;
    for (int c = tid; c < WIDTH; c += 256) { float v = xr[c]; ss += v * v; }
    red[tid] = ss;
    __syncthreads();
    for (int s2 = 128; s2 > 0; s2 >>= 1) {
        if (tid < s2) red[tid] += red[tid + s2];
        __syncthreads();
    }
    float inv = rsqrtf(red[0] / (float)WIDTH + 1e-6f);
    const float* sr = scale + (long)b * WIDTH;
    __nv_bfloat16* ohi = osp + (long)row * WIDTH;
    for (int c = tid; c < WIDTH; c += 256) {
        float v = xr[c] * inv * sr[c];
        __nv_bfloat16 hi, lo; bsplit(v, hi, lo);
        ohi[c] = hi; ohi[SP_N + c] = lo;
    }
}

// ================= RoPE: q (fp32 in, split out) + k (fp32 in-place) ========
__global__ void rope_both_kernel(const float* __restrict__ q, float* __restrict__ k,
                                 __nv_bfloat16* __restrict__ qsp) {
    int idx = blockIdx.x * blockDim.x + threadIdx.x;
    int total = (NB * NHEAD * AHORIZ + NROWS) * 128;
    if (idx >= total) return;
    int i = idx & 127;
    int rr = idx >> 7;
    float inv = __expf(-(float)i * 0.0719544577297821f);
    if (rr < NB * NHEAD * AHORIZ) {
        int s = rr % AHORIZ;
        float fr = (float)(PREF + s) * inv;
        float c, sn;
        sincosf(fr, &sn, &c);
        const float* base = q + (long)rr * HD;
        float x1 = base[i], x2 = base[i + 128];
        float y1 = x1 * c - x2 * sn, y2 = x2 * c + x1 * sn;
        __nv_bfloat16 h1, l1, h2, l2;
        bsplit(y1, h1, l1); bsplit(y2, h2, l2);
        __nv_bfloat16* dst = qsp + (long)rr * HD;
        dst[i] = h1; dst[i + 128] = h2;
        dst[SP_Q + i] = l1; dst[SP_Q + i + 128] = l2;
    } else {
        int rk = rr - NB * NHEAD * AHORIZ;
        int s = rk % AHORIZ;
        float fr = (float)(PREF + s) * inv;
        float c, sn;
        sincosf(fr, &sn, &c);
        float* base = k + (long)rk * HD;
        float x1 = base[i], x2 = base[i + 128];
        base[i] = x1 * c - x2 * sn;
        base[i + 128] = x2 * c + x1 * sn;
    }
}

// ================= softmax -> split bf16 planes =================
__global__ void softmax_kernel(const float* __restrict__ sc, __nv_bfloat16* __restrict__ psp) {
    long row = blockIdx.x;
    const float* r = sc + row * 1024;
    __shared__ float red[256];
    __shared__ float ex[1024];
    int tid = threadIdx.x;
    float mx = -3.4e38f;
    for (int t = tid; t < TOT; t += 256) mx = fmaxf(mx, r[t]);
    red[tid] = mx;
    __syncthreads();
    for (int s2 = 128; s2 > 0; s2 >>= 1) {
        if (tid < s2) red[tid] = fmaxf(red[tid], red[tid + s2]);
        __syncthreads();
    }
    mx = red[0];
    __syncthreads();
    float sum = 0.f;
    for (int t = tid; t < TOT; t += 256) { float e = __expf(r[t] - mx); ex[t] = e; sum += e; }
    red[tid] = sum;
    __syncthreads();
    for (int s2 = 128; s2 > 0; s2 >>= 1) {
        if (tid < s2) red[tid] += red[tid + s2];
        __syncthreads();
    }
    float inv = __fdividef(1.f, red[0]);
    __nv_bfloat16* dst = psp + row * 1024;
    for (int t = tid; t < TOT; t += 256) {
        float v = ex[t] * inv;
        __nv_bfloat16 hi, lo; bsplit(v, hi, lo);
        dst[t] = hi; dst[SP_P + t] = lo;
    }
    __nv_bfloat16 z = __float2bfloat16(0.f);
    for (int t = TOT + tid; t < 1024; t += 256) { dst[t] = z; dst[SP_P + t] = z; }
}

// ================= host driver =================
#define SMEM_128 (4 * 128 * ASTR * 2 + 4 * 32 * BSTR * 2)
#define SMEM_64  (4 * 64 * ASTR * 2 + 4 * 32 * BSTR * 2)
#define SMEM_GG  (4 * 64 * ASTR * 2 + 8 * 32 * BSTR * 2)

extern "C" void kernel_launch(void* const* d_in, const int* in_sizes, int n_in,
                              void* d_out, int out_size) {
    (void)in_sizes; (void)n_in; (void)out_size;
    const float* past_keys   = (const float*)d_in[1];
    const float* past_values = (const float*)d_in[2];
    const float* x_t         = (const float*)d_in[3];
    const float* timestep    = (const float*)d_in[4];
    const float* w_act_in    = (const float*)d_in[5];
    const float* b_act_in    = (const float*)d_in[6];
    const float* w_tin       = (const float*)d_in[7];
    const float* b_tin       = (const float*)d_in[8];
    const float* w_tout      = (const float*)d_in[9];
    const float* b_tout      = (const float*)d_in[10];
    const float* w_act_out   = (const float*)d_in[11];
    const float* b_act_out   = (const float*)d_in[12];
    const float* wq          = (const float*)d_in[13];
    const float* wk          = (const float*)d_in[14];
    const float* wv          = (const float*)d_in[15];
    const float* wo          = (const float*)d_in[16];
    const float* w_gate      = (const float*)d_in[17];
    const float* w_up        = (const float*)d_in[18];
    const float* w_down      = (const float*)d_in[19];
    const float* ln1_w       = (const float*)d_in[20];
    const float* ln1_ada     = (const float*)d_in[21];
    const float* ln2_w       = (const float*)d_in[22];
    const float* ln2_ada     = (const float*)d_in[23];
    const float* fin_w       = (const float*)d_in[24];
    const float* fin_ada     = (const float*)d_in[25];
    float* out = (float*)d_out;

    cudaFuncSetAttribute(mma_gemm<128, true>, cudaFuncAttributeMaxDynamicSharedMemorySize, SMEM_128);
    cudaFuncSetAttribute(mma_gemm<64, true>, cudaFuncAttributeMaxDynamicSharedMemorySize, SMEM_64);
    cudaFuncSetAttribute(mma_gemm<64, false>, cudaFuncAttributeMaxDynamicSharedMemorySize, SMEM_64);
    cudaFuncSetAttribute(mma_gemm_geglu, cudaFuncAttributeMaxDynamicSharedMemorySize, SMEM_GG);

    float *p_time, *p_t1, *p_cond, *p_s1, *p_s2, *p_fs, *p_h, *p_q, *p_k, *p_v, *p_sc;
    __nv_bfloat16 *p_nsp, *p_qsp, *p_psp, *p_attsp, *p_actsp;
    cudaGetSymbolAddress((void**)&p_time, g_time_emb);
    cudaGetSymbolAddress((void**)&p_t1, g_t1);
    cudaGetSymbolAddress((void**)&p_cond, g_cond);
    cudaGetSymbolAddress((void**)&p_s1, g_scale1);
    cudaGetSymbolAddress((void**)&p_s2, g_scale2);
    cudaGetSymbolAddress((void**)&p_fs, g_fscale);
    cudaGetSymbolAddress((void**)&p_h, g_h);
    cudaGetSymbolAddress((void**)&p_q, g_q);
    cudaGetSymbolAddress((void**)&p_k, g_k);
    cudaGetSymbolAddress((void**)&p_v, g_v);
    cudaGetSymbolAddress((void**)&p_sc, g_scores);
    cudaGetSymbolAddress((void**)&p_nsp, g_nsp);
    cudaGetSymbolAddress((void**)&p_qsp, g_qsp);
    cudaGetSymbolAddress((void**)&p_psp, g_psp);
    cudaGetSymbolAddress((void**)&p_attsp, g_attsp);
    cudaGetSymbolAddress((void**)&p_actsp, g_actsp);

    auto gemm64f = [&](const float* A, long lda, const float* B, long ldb,
                       float* C, long ldc, int M, int N, int K,
                       const float* aux, int ep, float alpha) {
        dim3 g((N + 63) / 64, (M + 63) / 64, 1);
        mma_gemm<64, false><<<g, 256, SMEM_64>>>(
            A, lda, 0, 0, B, ldb, 0, 0, 0, 0, 0, 0,
            C, ldc, 0, 0, 0, 0, 0, 0, 0,
            M, K, 1, 0, BMODE_NORMAL,
            1 << 30, 1 << 30, N, 0, 0, aux, ep, alpha, 0);
    };
    auto gemm128s = [&](const __nv_bfloat16* A, long lda, long spA,
                        const float* B, long ldb,
                        float* C, long ldc, int M, int N, int K, int nk,
                        const float* aux, int ep, float alpha) {
        dim3 g((N + 63) / 64, (M + 127) / 128, nk);
        mma_gemm<128, true><<<g, 256, SMEM_128>>>(
            A, lda, 0, spA, B, ldb, 0, 0, 0, 0, 0, 0,
            C, ldc, 0, 0, 0, 0, 0, 0, 0,
            M, K, nk, 0, BMODE_NORMAL,
            1 << 30, 1 << 30, N, 0, 0, aux, ep, alpha, 0);
    };

    // --- prologue ---
    time_emb_kernel<<<NB, 512>>>(timestep, p_time);
    gemm64f(p_time, WIDTH, w_tin, WIDTH, p_t1, WIDTH, NB, WIDTH, WIDTH, b_tin, EP_BIAS_SILU, 0.f);
    gemm64f(p_t1, WIDTH, w_tout, WIDTH, p_cond, WIDTH, NB, WIDTH, WIDTH, b_tout, EP_BIAS_SILU, 0.f);
    condinit_kernel<<<((2 * NLAYER + 1) * WIDTH + 255) / 256, 256>>>(ln1_w, ln2_w, fin_w, p_s1, p_s2, p_fs);
    condacc_kernel<<<dim3(8, 2 * NLAYER + 1), 512>>>(p_cond, ln1_ada, ln2_ada, fin_ada, p_s1, p_s2, p_fs);
    gemm64f(x_t, ADIM, w_act_in, WIDTH, p_h, WIDTH, NROWS, WIDTH, ADIM, b_act_in, EP_BIAS_SCALE, 32.f);

    for (int l = 0; l < NLAYER; l++) {
        const float* kpref = past_keys + (long)l * NB * PREF * HD;
        const float* vpref = past_values + (long)l * NB * PREF * HD;
        const float* wq_l = wq + (long)l * WIDTH * NHEAD * HD;
        const float* wk_l = wk + (long)l * WIDTH * HD;
        const float* wv_l = wv + (long)l * WIDTH * HD;
        const float* wo_l = wo + (long)l * NHEAD * HD * WIDTH;
        const float* wg_l = w_gate + (long)l * WIDTH * MLPD;
        const float* wu_l = w_up + (long)l * WIDTH * MLPD;
        const float* wd_l = w_down + (long)l * MLPD * WIDTH;

        adarms_kernel<<<NROWS, 256>>>(p_h, p_s1 + (long)l * NB * WIDTH, p_nsp);

        // fused QKV (BM=64): x [0,32)->q (remap), [32,36)->k, [36,40)->v
        {
            dim3 g(40, 4, 1);
            mma_gemm<64, true><<<g, 256, SMEM_64>>>(
                p_nsp, WIDTH, 0, SP_N,
                wq_l, NHEAD * HD, 0, wk_l, HD, 0, wv_l, HD,
                p_q, 0, p_k, HD, p_v, HD, 0, 0, 0,
                NROWS, WIDTH, 1, 0, BMODE_NORMAL,
                32, 36, NHEAD * HD, HD, HD, 0, EP_NONE, 0.f, 1);
        }

        rope_both_kernel<<<((NB * NHEAD * AHORIZ + NROWS) * 128 + 255) / 256, 256>>>(p_q, p_k, p_qsp);

        // scores: per-b M=400 (BM=64), B = K^T segments
        {
            dim3 g((TOT + 63) / 64, 7, NB);
            mma_gemm<64, true><<<g, 256, SMEM_64>>>(
                p_qsp, HD, (long)NHEAD * AHORIZ * HD, SP_Q,
                kpref, HD, (long)PREF * HD,
                p_k, HD, (long)AHORIZ * HD, 0, 0,
                p_sc, 1024, 0, 0, 0, 0,
                (long)NHEAD * AHORIZ * 1024, 0, 0,
                NHEAD * AHORIZ, HD, 1, TOT, BMODE_TRANS_SEG,
                1 << 30, 1 << 30, TOT, 0, 0, 0, EP_SCALE, 0.0625f, 0);
        }

        softmax_kernel<<<NB * NHEAD * AHORIZ, 256>>>(p_sc, p_psp);

        // PV (BM=64): per-b M=400, B = V segments; split-write att [s][h][d]
        {
            dim3 g(HD / 64, 7, NB);
            mma_gemm<64, true><<<g, 256, SMEM_64>>>(
                p_psp, 1024, (long)NHEAD * AHORIZ * 1024, SP_P,
                vpref, HD, (long)PREF * HD,
                p_v, HD, (long)AHORIZ * HD, 0, 0,
                0, 0, 0, 0, 0, 0,
                (long)AHORIZ * NHEAD * HD, p_attsp, SP_ATT,
                NHEAD * AHORIZ, 1024, 1, TOT, BMODE_SEG,
                1 << 30, 1 << 30, HD, 0, 0, 0, EP_SPLIT, 0.f, 2);
        }

        // output proj, split-K=8 (256 blocks: fills SMs), accumulate into h
        gemm128s(p_attsp, NHEAD * HD, SP_ATT, wo_l, WIDTH, p_h, WIDTH,
                 NROWS, WIDTH, NHEAD * HD, 8, 0, EP_ACC, 0.f);

        adarms_kernel<<<NROWS, 256>>>(p_h, p_s2 + (long)l * NB * WIDTH, p_nsp);

        // fused up+gate+GEGLU: actsp = split(gelu(A@wg) * (A@wu))
        {
            dim3 g(MLPD / 64, 4, 1);
            mma_gemm_geglu<<<g, 256, SMEM_GG>>>(
                p_nsp, WIDTH, SP_N,
                wu_l, wg_l, MLPD,
                p_actsp, MLPD, SP_ACT,
                NROWS, WIDTH);
        }

        // down proj, split-K=8 (256 blocks: fills SMs), accumulate into h
        gemm128s(p_actsp, MLPD, SP_ACT, wd_l, WIDTH, p_h, WIDTH,
                 NROWS, WIDTH, MLPD, 8, 0, EP_ACC, 0.f);
    }

    adarms_kernel<<<NROWS, 256>>>(p_h, p_fs, p_nsp);
    {
        dim3 g(1, (NROWS + 63) / 64, 1);
        mma_gemm<64, true><<<g, 256, SMEM_64>>>(
            p_nsp, WIDTH, 0, SP_N,
            w_act_out, ADIM, 0, 0, 0, 0, 0, 0,
            out, ADIM, 0, 0, 0, 0, 0, 0, 0,
            NROWS, WIDTH, 1, 0, BMODE_NORMAL,
            1 << 30, 1 << 30, ADIM, 0, 0, b_act_out, EP_BIAS, 0.f, 0);
    }
}